// round 14
// baseline (speedup 1.0000x reference)
#include <cuda_runtime.h>
#include <cstdint>
#include <cstddef>

#define N_PTS     200000
#define F_DIM     64
#define K_CL      256
#define MAX_ITERS 10
#define NSEG      256                              /* sort segments */
#define CHUNKB    ((N_PTS + NSEG - 1) / NSEG)      /* 782 */
#define NPAIR     (N_PTS / 2)
#define FLT_BIG   3.402823466e38f

typedef unsigned long long u64;

// ---------------- device scratch (static: no runtime allocation) ----------------
__device__ __align__(16) float g_centers[K_CL * F_DIM];
__device__ float g_csq[K_CL];
__device__ float g_xsq[N_PTS];
__device__ int   g_order[N_PTS];                 // points sorted stably by label
__device__ int   g_bhist[NSEG][K_CL];
__device__ int   g_bbase[NSEG][K_CL];
__device__ int   g_counts[K_CL];
__device__ int   g_cbase[K_CL];

// ---------------- f32x2 helpers: per-lane IEEE fp32 rn (== scalar fmaf per lane) --
__device__ __forceinline__ u64 pack2(float lo, float hi) {
    u64 r; asm("mov.b64 %0, {%1,%2};" : "=l"(r) : "f"(lo), "f"(hi)); return r;
}
__device__ __forceinline__ void unpack2(u64 v, float& lo, float& hi) {
    asm("mov.b64 {%0,%1}, %2;" : "=f"(lo), "=f"(hi) : "l"(v));
}
__device__ __forceinline__ u64 fma2(u64 a, u64 b, u64 c) {
    u64 d; asm("fma.rn.f32x2 %0, %1, %2, %3;" : "=l"(d) : "l"(a), "l"(b), "l"(c)); return d;
}

// ---------------- row reduce of sum(v*v): LLVM LV on Neoverse V2 ------------------
// VF=4, IC=4 (V2 max interleave): four 4-lane vector accumulators, vector
// iteration i consumes chunks 4i..4i+3 (acc_m gets elements 16i+4m+l), FUSED
// fmla. Parts combined in LV's serial chain ((a0+a1)+a2)+a3 per lane, then
// AArch64 faddp adjacent-pairs horizontal: (s0+s1)+(s2+s3).
__device__ __forceinline__ float rowsq_ref(const float* __restrict__ r) {
    float A0[4] = {0.f, 0.f, 0.f, 0.f};
    float A1[4] = {0.f, 0.f, 0.f, 0.f};
    float A2[4] = {0.f, 0.f, 0.f, 0.f};
    float A3[4] = {0.f, 0.f, 0.f, 0.f};
#pragma unroll
    for (int i = 0; i < F_DIM / 16; i++) {
#pragma unroll
        for (int l = 0; l < 4; l++) {
            float v0 = r[16 * i + 0  + l];
            float v1 = r[16 * i + 4  + l];
            float v2 = r[16 * i + 8  + l];
            float v3 = r[16 * i + 12 + l];
            A0[l] = __fmaf_rn(v0, v0, A0[l]);
            A1[l] = __fmaf_rn(v1, v1, A1[l]);
            A2[l] = __fmaf_rn(v2, v2, A2[l]);
            A3[l] = __fmaf_rn(v3, v3, A3[l]);
        }
    }
    float s[4];
#pragma unroll
    for (int l = 0; l < 4; l++)                     // ((a0+a1)+a2)+a3 per lane
        s[l] = __fadd_rn(__fadd_rn(__fadd_rn(A0[l], A1[l]), A2[l]), A3[l]);
    return __fadd_rn(__fadd_rn(s[0], s[1]), __fadd_rn(s[2], s[3]));  // faddp adjacent
}

// ---------------- init: copy centers; xsq[n] (computed once, like the reference) --
__global__ void k_init(const float* __restrict__ x, const float* __restrict__ c0) {
    int i = blockIdx.x * blockDim.x + threadIdx.x;
    if (i < K_CL * F_DIM) g_centers[i] = c0[i];
    if (i < N_PTS) g_xsq[i] = rowsq_ref(x + (size_t)i * F_DIM);
}

// ---------------- ||c_k||^2 via the identical reduce shape ------------------------
__global__ void k_csq_kernel() {
    int k = threadIdx.x;                             // 256 threads, 1 block
    g_csq[k] = rowsq_ref(g_centers + k * F_DIM);
}

// ---------------- assignment ------------------------------------------------------
// dot(point, center) = STRICT SERIAL fused-FMA chain over f=0..63 (Eigen gebp
// order). f32x2 packs 2 points per thread (per-lane rn == scalar fmaf).
// All 256 centers splatted (c,c) in 128 KB smem; warp-uniform LDS -> broadcast.
// 8 independent center-chains interleaved to hide FFMA2 latency.
__global__ void __launch_bounds__(256) k_assign(
        const float* __restrict__ x, float* __restrict__ labels) {
    extern __shared__ unsigned char dynsmem[];
    u64*   csp = (u64*)dynsmem;                      // [K_CL*F_DIM] splat pairs 128 KB
    float* scq = (float*)(csp + K_CL * F_DIM);       // [K_CL]

    const int tid = threadIdx.x;
    for (int i = tid; i < K_CL * F_DIM; i += 256) {
        float c = g_centers[i];
        csp[i] = pack2(c, c);
    }
    for (int i = tid; i < K_CL; i += 256) scq[i] = g_csq[i];
    __syncthreads();

    for (int p = blockIdx.x * 256 + tid; p < NPAIR; p += gridDim.x * 256) {
        const float4* xr = (const float4*)(x + (size_t)p * (2 * F_DIM));
        u64 xv[F_DIM];
#pragma unroll
        for (int q = 0; q < F_DIM / 4; q++) {
            float4 a = xr[q];                  // point 2p
            float4 b = xr[q + F_DIM / 4];      // point 2p+1
            xv[4 * q + 0] = pack2(a.x, b.x);
            xv[4 * q + 1] = pack2(a.y, b.y);
            xv[4 * q + 2] = pack2(a.z, b.z);
            xv[4 * q + 3] = pack2(a.w, b.w);
        }
        const float xsq0 = g_xsq[2 * p];
        const float xsq1 = g_xsq[2 * p + 1];

        float best0 = FLT_BIG, best1 = FLT_BIG;
        int   bi0 = 0, bi1 = 0;

#pragma unroll 1
        for (int kg = 0; kg < K_CL / 8; kg++) {
            const ulonglong2* cp = (const ulonglong2*)(csp + kg * 8 * F_DIM);
            u64 a0 = 0ull, a1 = 0ull, a2 = 0ull, a3 = 0ull;
            u64 a4 = 0ull, a5 = 0ull, a6 = 0ull, a7 = 0ull;
#pragma unroll
            for (int h = 0; h < F_DIM / 2; h++) {    // each chain: serial f ascending
                ulonglong2 c0 = cp[h];
                ulonglong2 c1 = cp[32 + h];
                ulonglong2 c2 = cp[64 + h];
                ulonglong2 c3 = cp[96 + h];
                ulonglong2 c4 = cp[128 + h];
                ulonglong2 c5 = cp[160 + h];
                ulonglong2 c6 = cp[192 + h];
                ulonglong2 c7 = cp[224 + h];
                a0 = fma2(xv[2 * h], c0.x, a0); a0 = fma2(xv[2 * h + 1], c0.y, a0);
                a1 = fma2(xv[2 * h], c1.x, a1); a1 = fma2(xv[2 * h + 1], c1.y, a1);
                a2 = fma2(xv[2 * h], c2.x, a2); a2 = fma2(xv[2 * h + 1], c2.y, a2);
                a3 = fma2(xv[2 * h], c3.x, a3); a3 = fma2(xv[2 * h + 1], c3.y, a3);
                a4 = fma2(xv[2 * h], c4.x, a4); a4 = fma2(xv[2 * h + 1], c4.y, a4);
                a5 = fma2(xv[2 * h], c5.x, a5); a5 = fma2(xv[2 * h + 1], c5.y, a5);
                a6 = fma2(xv[2 * h], c6.x, a6); a6 = fma2(xv[2 * h + 1], c6.y, a6);
                a7 = fma2(xv[2 * h], c7.x, a7); a7 = fma2(xv[2 * h + 1], c7.y, a7);
            }
            u64 dv[8] = {a0, a1, a2, a3, a4, a5, a6, a7};
#pragma unroll
            for (int j = 0; j < 8; j++) {            // ascending k, strict <
                float dl, dh; unpack2(dv[j], dl, dh);
                float cq = scq[kg * 8 + j];
                float e0 = __fadd_rn(__fmaf_rn(dl, -2.0f, xsq0), cq);
                float e1 = __fadd_rn(__fmaf_rn(dh, -2.0f, xsq1), cq);
                int k = kg * 8 + j;
                if (e0 < best0) { best0 = e0; bi0 = k; }
                if (e1 < best1) { best1 = e1; bi1 = k; }
            }
        }
        labels[2 * p]     = (float)bi0;   // float32 output
        labels[2 * p + 1] = (float)bi1;
    }
}

// ---------------- stable counting sort of points by label -------------------------
__global__ void k_hist(const float* __restrict__ labels) {
    __shared__ int h[K_CL];
    const int b = blockIdx.x, tid = threadIdx.x;
    for (int i = tid; i < K_CL; i += 256) h[i] = 0;
    __syncthreads();
    const int s = b * CHUNKB, e = min(N_PTS, s + CHUNKB), m = e - s;
    for (int i = tid; i < m; i += 256) atomicAdd(&h[(int)labels[s + i]], 1);
    __syncthreads();
    for (int i = tid; i < K_CL; i += 256) g_bhist[b][i] = h[i];
}

__global__ void k_scan() {
    __shared__ int stot[K_CL], sbase[K_CL];
    const int k = threadIdx.x;                       // 256 threads, 1 block
    int tot = 0;
    for (int b = 0; b < NSEG; b++) tot += g_bhist[b][k];
    stot[k] = tot;
    __syncthreads();
    if (k == 0) {
        int base = 0;
        for (int i = 0; i < K_CL; i++) { sbase[i] = base; base += stot[i]; }
    }
    __syncthreads();
    int run = sbase[k];
    for (int b = 0; b < NSEG; b++) { g_bbase[b][k] = run; run += g_bhist[b][k]; }
    g_counts[k] = stot[k];
    g_cbase[k]  = sbase[k];
}

__global__ void k_place(const float* __restrict__ labels) {
    __shared__ int slab[CHUNKB];
    __shared__ int cur[K_CL];
    const int b = blockIdx.x, tid = threadIdx.x;
    const int s = b * CHUNKB, e = min(N_PTS, s + CHUNKB), m = e - s;
    for (int i = tid; i < m; i += 256) slab[i] = (int)labels[s + i];
    for (int i = tid; i < K_CL; i += 256) cur[i] = g_bbase[b][i];
    __syncthreads();
    if (tid == 0) {                                  // stable: ascending n within block
        for (int i = 0; i < m; i++) {
            int k = slab[i];
            g_order[cur[k]++] = s + i;
        }
    }
}

// ---------------- per-cluster serial sums (global point order) + center update ----
// sums[k][f] = sequential adds with n ascending — exact scatter-add order.
__global__ void k_sums(const float* __restrict__ x) {
    __shared__ int sidx[2048];
    const int k = blockIdx.x;                        // 256 blocks
    const int f = threadIdx.x;                       // 64 threads
    const int base = g_cbase[k];
    const int cnt  = g_counts[k];
    float acc = 0.f;
    for (int off = 0; off < cnt; off += 2048) {
        const int m = min(2048, cnt - off);
        __syncthreads();
        for (int i = threadIdx.x; i < m; i += 64) sidx[i] = g_order[base + off + i];
        __syncthreads();
        int i = 0;
        for (; i + 8 <= m; i += 8) {                 // batch loads (MLP), serial adds
            float v0 = x[(size_t)sidx[i + 0] * F_DIM + f];
            float v1 = x[(size_t)sidx[i + 1] * F_DIM + f];
            float v2 = x[(size_t)sidx[i + 2] * F_DIM + f];
            float v3 = x[(size_t)sidx[i + 3] * F_DIM + f];
            float v4 = x[(size_t)sidx[i + 4] * F_DIM + f];
            float v5 = x[(size_t)sidx[i + 5] * F_DIM + f];
            float v6 = x[(size_t)sidx[i + 6] * F_DIM + f];
            float v7 = x[(size_t)sidx[i + 7] * F_DIM + f];
            acc = __fadd_rn(acc, v0); acc = __fadd_rn(acc, v1);
            acc = __fadd_rn(acc, v2); acc = __fadd_rn(acc, v3);
            acc = __fadd_rn(acc, v4); acc = __fadd_rn(acc, v5);
            acc = __fadd_rn(acc, v6); acc = __fadd_rn(acc, v7);
        }
        for (; i < m; i++)
            acc = __fadd_rn(acc, x[(size_t)sidx[i] * F_DIM + f]);
    }
    if (cnt > 0)
        g_centers[k * F_DIM + f] = __fdiv_rn(acc, (float)cnt);  // empty keeps old
}

// ---------------- launch ----------------
extern "C" void kernel_launch(void* const* d_in, const int* in_sizes, int n_in,
                              void* d_out, int out_size) {
    const float* x  = nullptr;
    const float* c0 = nullptr;
    for (int i = 0; i < n_in; i++) {
        if (in_sizes[i] == N_PTS * F_DIM)      x  = (const float*)d_in[i];
        else if (in_sizes[i] == K_CL * F_DIM)  c0 = (const float*)d_in[i];
    }
    if (!x)  x  = (const float*)d_in[0];
    if (!c0) c0 = (const float*)d_in[1];
    float* labels = (float*)d_out;                   // __output__ is float32

    int dev = 0, nsm = 0;
    cudaGetDevice(&dev);
    if (cudaDeviceGetAttribute(&nsm, cudaDevAttrMultiProcessorCount, dev) != cudaSuccess || nsm <= 0)
        nsm = 148;

    const size_t asmem = (size_t)K_CL * F_DIM * sizeof(u64) + K_CL * sizeof(float); // ~129 KB
    cudaFuncSetAttribute(k_assign, cudaFuncAttributeMaxDynamicSharedMemorySize, (int)asmem);

    k_init<<<(N_PTS + 255) / 256, 256>>>(x, c0);
    for (int it = 0; it < MAX_ITERS; it++) {
        k_csq_kernel<<<1, K_CL>>>();
        k_assign<<<nsm, 256, asmem>>>(x, labels);
        k_hist<<<NSEG, 256>>>(labels);
        k_scan<<<1, K_CL>>>();
        k_place<<<NSEG, 256>>>(labels);
        k_sums<<<K_CL, F_DIM>>>(x);
    }
}

// round 15
// speedup vs baseline: 1.9866x; 1.9866x over previous
#include <cuda_runtime.h>
#include <cstdint>
#include <cstddef>

#define N_PTS     200000
#define F_DIM     64
#define K_CL      256
#define MAX_ITERS 10
#define NSEG      256                              /* sort segments */
#define CHUNKB    ((N_PTS + NSEG - 1) / NSEG)      /* 782 */
#define NPAIR     (N_PTS / 2)                      /* 100000 */
#define NTILE     (NPAIR / 32)                     /* 3125 tiles of 32 pairs */
#define FLT_BIG   3.402823466e38f

/* smem layout constants (u64 units) */
#define C_GRP_STRIDE 514                           /* 8 centers*64 + 2 pad  */
#define C_TOTAL      (32 * C_GRP_STRIDE)           /* 16448 u64 = 128.5 KB  */
#define X_STRIDE     66                            /* 64 + 2 pad, 16B-align */
#define X_TOTAL      (32 * X_STRIDE)               /* 2112 u64 = 16.5 KB    */

typedef unsigned long long u64;

// ---------------- device scratch (static: no runtime allocation) ----------------
__device__ __align__(16) float g_centers[K_CL * F_DIM];
__device__ float g_csq[K_CL];
__device__ float g_xsq[N_PTS];
__device__ int   g_order[N_PTS];                 // points sorted stably by label
__device__ int   g_bhist[NSEG][K_CL];
__device__ int   g_bbase[NSEG][K_CL];
__device__ int   g_counts[K_CL];
__device__ int   g_cbase[K_CL];

// ---------------- f32x2 helpers: per-lane IEEE fp32 rn (== scalar fmaf per lane) --
__device__ __forceinline__ u64 pack2(float lo, float hi) {
    u64 r; asm("mov.b64 %0, {%1,%2};" : "=l"(r) : "f"(lo), "f"(hi)); return r;
}
__device__ __forceinline__ void unpack2(u64 v, float& lo, float& hi) {
    asm("mov.b64 {%0,%1}, %2;" : "=f"(lo), "=f"(hi) : "l"(v));
}
__device__ __forceinline__ u64 fma2(u64 a, u64 b, u64 c) {
    u64 d; asm("fma.rn.f32x2 %0, %1, %2, %3;" : "=l"(d) : "l"(a), "l"(b), "l"(c)); return d;
}

// ---------------- row reduce of sum(v*v): Neoverse V2 LV shape (VERIFIED) ---------
// VF=4, IC=4: four 4-lane accumulators, FUSED fmla, ((a0+a1)+a2)+a3 per lane,
// faddp adjacent-pairs horizontal: (s0+s1)+(s2+s3).  DO NOT CHANGE — bit-exact.
__device__ __forceinline__ float rowsq_ref(const float* __restrict__ r) {
    float A0[4] = {0.f, 0.f, 0.f, 0.f};
    float A1[4] = {0.f, 0.f, 0.f, 0.f};
    float A2[4] = {0.f, 0.f, 0.f, 0.f};
    float A3[4] = {0.f, 0.f, 0.f, 0.f};
#pragma unroll
    for (int i = 0; i < F_DIM / 16; i++) {
#pragma unroll
        for (int l = 0; l < 4; l++) {
            float v0 = r[16 * i + 0  + l];
            float v1 = r[16 * i + 4  + l];
            float v2 = r[16 * i + 8  + l];
            float v3 = r[16 * i + 12 + l];
            A0[l] = __fmaf_rn(v0, v0, A0[l]);
            A1[l] = __fmaf_rn(v1, v1, A1[l]);
            A2[l] = __fmaf_rn(v2, v2, A2[l]);
            A3[l] = __fmaf_rn(v3, v3, A3[l]);
        }
    }
    float s[4];
#pragma unroll
    for (int l = 0; l < 4; l++)
        s[l] = __fadd_rn(__fadd_rn(__fadd_rn(A0[l], A1[l]), A2[l]), A3[l]);
    return __fadd_rn(__fadd_rn(s[0], s[1]), __fadd_rn(s[2], s[3]));
}

// ---------------- init: copy centers; xsq[n] computed ONCE (matches reference) ----
__global__ void k_init(const float* __restrict__ x, const float* __restrict__ c0) {
    int i = blockIdx.x * blockDim.x + threadIdx.x;
    if (i < K_CL * F_DIM) g_centers[i] = c0[i];
    if (i < N_PTS) g_xsq[i] = rowsq_ref(x + (size_t)i * F_DIM);
}

// ---------------- ||c_k||^2 via the identical reduce shape ------------------------
__global__ void k_csq_kernel() {
    int k = threadIdx.x;                             // 256 threads, 1 block
    g_csq[k] = rowsq_ref(g_centers + k * F_DIM);
}

// ---------------- assignment: register-tiled co-op kernel -------------------------
// Block tile: 32 pairs (64 points) x 256 centers. 512 threads, 16 warps.
// Thread = 2 pair-slots (s, s+16) x 8 centers (group g): 16 u64 accumulators.
// Per (pair,center): UNCHANGED serial fused fma2 chain over f=0..63 ascending.
// x pair-packed in smem (stride 66 u64); centers splat (c,c) in padded groups
// (stride 514 u64) so the two half-warp broadcast addresses avoid bank clash.
// Cross-thread argmin staged in smem, combined over ascending center-groups.
__global__ void __launch_bounds__(512, 1) k_assign(
        const float* __restrict__ x, float* __restrict__ labels) {
    extern __shared__ unsigned char dynsmem[];
    u64*   csp = (u64*)dynsmem;                      // [32 groups][514]
    u64*   xsm = csp + C_TOTAL;                      // [32 pairs][66]
    float* scq = (float*)(xsm + X_TOTAL);            // [256]
    float* sbv = scq + K_CL;                         // [64 pts][33]
    int*   sbi = (int*)(sbv + 64 * 33);              // [64 pts][33]

    const int tid  = threadIdx.x;
    const int w    = tid >> 5;
    const int lane = tid & 31;
    const int s    = lane & 15;                      // pair-slots s and s+16
    const int g    = (w << 1) | (lane >> 4);         // center group 0..31

    for (int i = tid; i < K_CL * F_DIM; i += 512) {
        int c = i >> 6, f = i & 63;
        float cv = g_centers[i];
        csp[(c >> 3) * C_GRP_STRIDE + (c & 7) * 64 + f] = pack2(cv, cv);
    }
    for (int i = tid; i < K_CL; i += 512) scq[i] = g_csq[i];
    __syncthreads();

    const u64* cbase = csp + g * C_GRP_STRIDE;

    for (int T = blockIdx.x; T < NTILE; T += gridDim.x) {
        const int p0 = T * 32;                       // first pair of tile
        // ---- stage x tile: thread = (pair sp=tid>>4, float4-col c4=tid&15) ----
        {
            int sp = tid >> 4, c4 = tid & 15;
            const float4* r0 = (const float4*)(x + (size_t)(p0 + sp) * 2 * F_DIM);
            float4 a = r0[c4];                       // point 2(p0+sp)
            float4 b = r0[c4 + 16];                  // point 2(p0+sp)+1
            ulonglong2* dst = (ulonglong2*)(xsm + sp * X_STRIDE + c4 * 4);
            dst[0] = make_ulonglong2(pack2(a.x, b.x), pack2(a.y, b.y));
            dst[1] = make_ulonglong2(pack2(a.z, b.z), pack2(a.w, b.w));
        }
        float xsq0 = g_xsq[(p0 + s) * 2 + 0];
        float xsq1 = g_xsq[(p0 + s) * 2 + 1];
        float xsq2 = g_xsq[(p0 + s + 16) * 2 + 0];
        float xsq3 = g_xsq[(p0 + s + 16) * 2 + 1];
        __syncthreads();

        // ---- mainloop: 16 accumulators, serial f-ascending fused chains ----
        u64 acc0[8], acc1[8];
#pragma unroll
        for (int j = 0; j < 8; j++) { acc0[j] = 0ull; acc1[j] = 0ull; }
        const ulonglong2* xr0 = (const ulonglong2*)(xsm + s * X_STRIDE);
        const ulonglong2* xr1 = (const ulonglong2*)(xsm + (s + 16) * X_STRIDE);
#pragma unroll 4
        for (int f2 = 0; f2 < F_DIM / 2; f2++) {
            ulonglong2 xa = xr0[f2];                 // features 2f2, 2f2+1 pair s
            ulonglong2 xb = xr1[f2];                 // same, pair s+16
#pragma unroll
            for (int j = 0; j < 8; j++) {
                ulonglong2 cj = *(const ulonglong2*)(cbase + j * 64 + 2 * f2);
                acc0[j] = fma2(xa.x, cj.x, acc0[j]);   // f = 2f2
                acc0[j] = fma2(xa.y, cj.y, acc0[j]);   // f = 2f2+1
                acc1[j] = fma2(xb.x, cj.x, acc1[j]);
                acc1[j] = fma2(xb.y, cj.y, acc1[j]);
            }
        }

        // ---- epilogue: exact (xsq - 2*dot) + csq, strict < ascending j ----
        float bv0 = FLT_BIG, bv1 = FLT_BIG, bv2 = FLT_BIG, bv3 = FLT_BIG;
        int   bi0 = 0, bi1 = 0, bi2 = 0, bi3 = 0;
#pragma unroll
        for (int j = 0; j < 8; j++) {
            float cq = scq[g * 8 + j];
            int   k  = g * 8 + j;
            float dl, dh, el, eh;
            unpack2(acc0[j], dl, dh);
            el = __fadd_rn(__fmaf_rn(dl, -2.0f, xsq0), cq);
            eh = __fadd_rn(__fmaf_rn(dh, -2.0f, xsq1), cq);
            if (el < bv0) { bv0 = el; bi0 = k; }
            if (eh < bv1) { bv1 = eh; bi1 = k; }
            unpack2(acc1[j], dl, dh);
            el = __fadd_rn(__fmaf_rn(dl, -2.0f, xsq2), cq);
            eh = __fadd_rn(__fmaf_rn(dh, -2.0f, xsq3), cq);
            if (el < bv2) { bv2 = el; bi2 = k; }
            if (eh < bv3) { bv3 = eh; bi3 = k; }
        }
        sbv[(2 * s + 0)  * 33 + g] = bv0; sbi[(2 * s + 0)  * 33 + g] = bi0;
        sbv[(2 * s + 1)  * 33 + g] = bv1; sbi[(2 * s + 1)  * 33 + g] = bi1;
        sbv[(2 * s + 32) * 33 + g] = bv2; sbi[(2 * s + 32) * 33 + g] = bi2;
        sbv[(2 * s + 33) * 33 + g] = bv3; sbi[(2 * s + 33) * 33 + g] = bi3;
        __syncthreads();

        // ---- final per-point argmin over groups (ascending k => first-min) ----
        if (tid < 64) {
            float bbv = FLT_BIG; int bbi = 0;
#pragma unroll 8
            for (int gg = 0; gg < 32; gg++) {
                float v = sbv[tid * 33 + gg];
                int   i = sbi[tid * 33 + gg];
                if (v < bbv) { bbv = v; bbi = i; }
            }
            labels[T * 64 + tid] = (float)bbi;       // float32 output
        }
        __syncthreads();
    }
}

// ---------------- stable counting sort of points by label -------------------------
__global__ void k_hist(const float* __restrict__ labels) {
    __shared__ int h[K_CL];
    const int b = blockIdx.x, tid = threadIdx.x;
    for (int i = tid; i < K_CL; i += 256) h[i] = 0;
    __syncthreads();
    const int s = b * CHUNKB, e = min(N_PTS, s + CHUNKB), m = e - s;
    for (int i = tid; i < m; i += 256) atomicAdd(&h[(int)labels[s + i]], 1);
    __syncthreads();
    for (int i = tid; i < K_CL; i += 256) g_bhist[b][i] = h[i];
}

__global__ void k_scan() {
    __shared__ int stot[K_CL], sbase[K_CL];
    const int k = threadIdx.x;                       // 256 threads, 1 block
    int tot = 0;
    for (int b = 0; b < NSEG; b++) tot += g_bhist[b][k];
    stot[k] = tot;
    __syncthreads();
    if (k == 0) {
        int base = 0;
        for (int i = 0; i < K_CL; i++) { sbase[i] = base; base += stot[i]; }
    }
    __syncthreads();
    int run = sbase[k];
    for (int b = 0; b < NSEG; b++) { g_bbase[b][k] = run; run += g_bhist[b][k]; }
    g_counts[k] = stot[k];
    g_cbase[k]  = sbase[k];
}

__global__ void k_place(const float* __restrict__ labels) {
    __shared__ int slab[CHUNKB];
    __shared__ int cur[K_CL];
    const int b = blockIdx.x, tid = threadIdx.x;
    const int s = b * CHUNKB, e = min(N_PTS, s + CHUNKB), m = e - s;
    for (int i = tid; i < m; i += 256) slab[i] = (int)labels[s + i];
    for (int i = tid; i < K_CL; i += 256) cur[i] = g_bbase[b][i];
    __syncthreads();
    if (tid == 0) {                                  // stable: ascending n within block
        for (int i = 0; i < m; i++) {
            int k = slab[i];
            g_order[cur[k]++] = s + i;
        }
    }
}

// ---------------- per-cluster serial sums (global point order) + center update ----
__global__ void k_sums(const float* __restrict__ x) {
    __shared__ int sidx[2048];
    const int k = blockIdx.x;                        // 256 blocks
    const int f = threadIdx.x;                       // 64 threads
    const int base = g_cbase[k];
    const int cnt  = g_counts[k];
    float acc = 0.f;
    for (int off = 0; off < cnt; off += 2048) {
        const int m = min(2048, cnt - off);
        __syncthreads();
        for (int i = threadIdx.x; i < m; i += 64) sidx[i] = g_order[base + off + i];
        __syncthreads();
        int i = 0;
        for (; i + 8 <= m; i += 8) {                 // batch loads (MLP), serial adds
            float v0 = x[(size_t)sidx[i + 0] * F_DIM + f];
            float v1 = x[(size_t)sidx[i + 1] * F_DIM + f];
            float v2 = x[(size_t)sidx[i + 2] * F_DIM + f];
            float v3 = x[(size_t)sidx[i + 3] * F_DIM + f];
            float v4 = x[(size_t)sidx[i + 4] * F_DIM + f];
            float v5 = x[(size_t)sidx[i + 5] * F_DIM + f];
            float v6 = x[(size_t)sidx[i + 6] * F_DIM + f];
            float v7 = x[(size_t)sidx[i + 7] * F_DIM + f];
            acc = __fadd_rn(acc, v0); acc = __fadd_rn(acc, v1);
            acc = __fadd_rn(acc, v2); acc = __fadd_rn(acc, v3);
            acc = __fadd_rn(acc, v4); acc = __fadd_rn(acc, v5);
            acc = __fadd_rn(acc, v6); acc = __fadd_rn(acc, v7);
        }
        for (; i < m; i++)
            acc = __fadd_rn(acc, x[(size_t)sidx[i] * F_DIM + f]);
    }
    if (cnt > 0)
        g_centers[k * F_DIM + f] = __fdiv_rn(acc, (float)cnt);  // empty keeps old
}

// ---------------- launch ----------------
extern "C" void kernel_launch(void* const* d_in, const int* in_sizes, int n_in,
                              void* d_out, int out_size) {
    const float* x  = nullptr;
    const float* c0 = nullptr;
    for (int i = 0; i < n_in; i++) {
        if (in_sizes[i] == N_PTS * F_DIM)      x  = (const float*)d_in[i];
        else if (in_sizes[i] == K_CL * F_DIM)  c0 = (const float*)d_in[i];
    }
    if (!x)  x  = (const float*)d_in[0];
    if (!c0) c0 = (const float*)d_in[1];
    float* labels = (float*)d_out;                   // __output__ is float32

    int dev = 0, nsm = 0;
    cudaGetDevice(&dev);
    if (cudaDeviceGetAttribute(&nsm, cudaDevAttrMultiProcessorCount, dev) != cudaSuccess || nsm <= 0)
        nsm = 148;

    const size_t asmem = (size_t)(C_TOTAL + X_TOTAL) * sizeof(u64)
                       + K_CL * sizeof(float)
                       + 64 * 33 * (sizeof(float) + sizeof(int));   // ~163 KB
    cudaFuncSetAttribute(k_assign, cudaFuncAttributeMaxDynamicSharedMemorySize, (int)asmem);

    k_init<<<(N_PTS + 255) / 256, 256>>>(x, c0);
    for (int it = 0; it < MAX_ITERS; it++) {
        k_csq_kernel<<<1, K_CL>>>();
        k_assign<<<nsm, 512, asmem>>>(x, labels);
        k_hist<<<NSEG, 256>>>(labels);
        k_scan<<<1, K_CL>>>();
        k_place<<<NSEG, 256>>>(labels);
        k_sums<<<K_CL, F_DIM>>>(x);
    }
}

// round 16
// speedup vs baseline: 2.1671x; 1.0909x over previous
#include <cuda_runtime.h>
#include <cstdint>
#include <cstddef>

#define N_PTS     200000
#define F_DIM     64
#define K_CL      256
#define MAX_ITERS 10
#define NSEG      256                              /* sort segments */
#define CHUNKB    ((N_PTS + NSEG - 1) / NSEG)      /* 782 */
#define NTILE     (N_PTS / 64)                     /* 3125 tiles of 64 points */
#define FLT_BIG   3.402823466e38f

/* smem layout (u64 units) */
#define C_GRP_STRIDE 258                           /* 4 cpairs*64 + 2 pad   */
#define C_TOTAL      (32 * C_GRP_STRIDE)           /* 8256 u64 = 64.5 KB    */
#define X_STRIDE_F   66                            /* floats per x row      */

typedef unsigned long long u64;

// ---------------- device scratch (static: no runtime allocation) ----------------
__device__ __align__(16) float g_centers[K_CL * F_DIM];
__device__ float g_xsq[N_PTS];
__device__ int   g_order[N_PTS];                 // points sorted stably by label
__device__ int   g_bhist[NSEG][K_CL];
__device__ int   g_bbase[NSEG][K_CL];
__device__ int   g_counts[K_CL];
__device__ int   g_cbase[K_CL];

// ---------------- f32x2 helpers: per-lane IEEE fp32 rn (== scalar fmaf per lane) --
__device__ __forceinline__ u64 pack2(float lo, float hi) {
    u64 r; asm("mov.b64 %0, {%1,%2};" : "=l"(r) : "f"(lo), "f"(hi)); return r;
}
__device__ __forceinline__ u64 splat2(float v) {
    u64 r; asm("mov.b64 %0, {%1,%1};" : "=l"(r) : "f"(v)); return r;
}
__device__ __forceinline__ void unpack2(u64 v, float& lo, float& hi) {
    asm("mov.b64 {%0,%1}, %2;" : "=f"(lo), "=f"(hi) : "l"(v));
}
__device__ __forceinline__ u64 fma2(u64 a, u64 b, u64 c) {
    u64 d; asm("fma.rn.f32x2 %0, %1, %2, %3;" : "=l"(d) : "l"(a), "l"(b), "l"(c)); return d;
}

// ---------------- row reduce of sum(v*v): Neoverse V2 LV shape (VERIFIED R14) -----
// VF=4, IC=4, FUSED fmla, ((a0+a1)+a2)+a3 per lane, faddp (s0+s1)+(s2+s3).
// DO NOT CHANGE — bit-exact vs reference.
__device__ __forceinline__ float rowsq_ref(const float* __restrict__ r) {
    float A0[4] = {0.f, 0.f, 0.f, 0.f};
    float A1[4] = {0.f, 0.f, 0.f, 0.f};
    float A2[4] = {0.f, 0.f, 0.f, 0.f};
    float A3[4] = {0.f, 0.f, 0.f, 0.f};
#pragma unroll
    for (int i = 0; i < F_DIM / 16; i++) {
#pragma unroll
        for (int l = 0; l < 4; l++) {
            float v0 = r[16 * i + 0  + l];
            float v1 = r[16 * i + 4  + l];
            float v2 = r[16 * i + 8  + l];
            float v3 = r[16 * i + 12 + l];
            A0[l] = __fmaf_rn(v0, v0, A0[l]);
            A1[l] = __fmaf_rn(v1, v1, A1[l]);
            A2[l] = __fmaf_rn(v2, v2, A2[l]);
            A3[l] = __fmaf_rn(v3, v3, A3[l]);
        }
    }
    float s[4];
#pragma unroll
    for (int l = 0; l < 4; l++)
        s[l] = __fadd_rn(__fadd_rn(__fadd_rn(A0[l], A1[l]), A2[l]), A3[l]);
    return __fadd_rn(__fadd_rn(s[0], s[1]), __fadd_rn(s[2], s[3]));
}

// ---------------- init: copy centers; xsq[n] computed ONCE (matches reference) ----
__global__ void k_init(const float* __restrict__ x, const float* __restrict__ c0) {
    int i = blockIdx.x * blockDim.x + threadIdx.x;
    if (i < K_CL * F_DIM) g_centers[i] = c0[i];
    if (i < N_PTS) g_xsq[i] = rowsq_ref(x + (size_t)i * F_DIM);
}

// ---------------- assignment (csq fused into prologue) ----------------------------
// Block tile: 64 points x 256 centers. 512 threads.
// Thread = 4 points (q, q+16, q+32, q+48) x 8 centers (group g) via 16 u64
// accumulators acc[point][cpair], lanes = (center 2j, center 2j+1).
// Centers pre-packed PAIRWISE in smem (full-information LDS.128, broadcast);
// x splat (x_f,x_f) built in registers (mov.b64) from conflict-free LDS.64.
// Per (point,center): UNCHANGED serial fused fma2 chain over f=0..63 ascending.
__global__ void __launch_bounds__(512, 1) k_assign(
        const float* __restrict__ x, float* __restrict__ labels) {
    extern __shared__ unsigned char dynsmem[];
    u64*   csp = (u64*)dynsmem;                      // [32 grp][258] packed pairs
    float* xsm = (float*)(csp + C_TOTAL);            // [64 pts][66]
    float* scq = xsm + 64 * X_STRIDE_F;              // [256]
    float* sbv = scq + K_CL;                         // [64 pts][33]
    int*   sbi = (int*)(sbv + 64 * 33);              // [64 pts][33]

    const int tid  = threadIdx.x;
    const int w    = tid >> 5;
    const int lane = tid & 31;
    const int q    = lane & 15;                      // point slots q+16m
    const int g    = (w << 1) | (lane >> 4);         // center group 0..31

    // prologue: pairwise-packed centers + fused csq (identical rowsq_ref)
    for (int i = tid; i < K_CL * F_DIM; i += 512) {
        int c = i >> 6, f = i & 63;
        ((float*)csp)[(((c >> 3) * C_GRP_STRIDE + ((c & 7) >> 1) * 64 + f) << 1)
                      + (c & 1)] = g_centers[i];
    }
    for (int k = tid; k < K_CL; k += 512)
        scq[k] = rowsq_ref(g_centers + k * F_DIM);
    __syncthreads();

    const u64* cbase = csp + g * C_GRP_STRIDE;

    for (int T = blockIdx.x; T < NTILE; T += gridDim.x) {
        const int n0 = T * 64;                       // first point of tile
        // ---- stage x tile as plain floats, row stride 66 (bank-clean) ----
#pragma unroll
        for (int m = 0; m < 4; m++) {
            int idx = tid + m * 512;                 // 2048 float2 chunks
            int p = idx >> 5, c2 = idx & 31;
            float2 v = *(const float2*)(x + (size_t)(n0 + p) * F_DIM + 2 * c2);
            *(float2*)(xsm + p * X_STRIDE_F + 2 * c2) = v;
        }
        float xsq[4];
#pragma unroll
        for (int m = 0; m < 4; m++) xsq[m] = g_xsq[n0 + q + 16 * m];
        __syncthreads();

        // ---- mainloop: 16 chains, serial f-ascending fused fma2 ----
        u64 acc[4][4];
#pragma unroll
        for (int m = 0; m < 4; m++)
#pragma unroll
            for (int j2 = 0; j2 < 4; j2++) acc[m][j2] = 0ull;

#pragma unroll 4
        for (int f2 = 0; f2 < F_DIM / 2; f2++) {
            u64 xs0[4], xs1[4];
#pragma unroll
            for (int m = 0; m < 4; m++) {
                float2 v = *(const float2*)(xsm + (q + 16 * m) * X_STRIDE_F + 2 * f2);
                xs0[m] = splat2(v.x);                // feature 2f2
                xs1[m] = splat2(v.y);                // feature 2f2+1
            }
            ulonglong2 cj[4];
#pragma unroll
            for (int j2 = 0; j2 < 4; j2++)
                cj[j2] = *(const ulonglong2*)(cbase + j2 * 64 + 2 * f2);
#pragma unroll
            for (int m = 0; m < 4; m++)
#pragma unroll
                for (int j2 = 0; j2 < 4; j2++) {
                    acc[m][j2] = fma2(xs0[m], cj[j2].x, acc[m][j2]);  // f = 2f2
                    acc[m][j2] = fma2(xs1[m], cj[j2].y, acc[m][j2]);  // f = 2f2+1
                }
        }

        // ---- epilogue: exact (xsq - 2*dot) + csq, strict < ascending k ----
#pragma unroll
        for (int m = 0; m < 4; m++) {
            float bv = FLT_BIG; int bi = 0;
#pragma unroll
            for (int j2 = 0; j2 < 4; j2++) {
                float d0, d1;
                unpack2(acc[m][j2], d0, d1);
                int k0 = 8 * g + 2 * j2;
                float e0 = __fadd_rn(__fmaf_rn(d0, -2.0f, xsq[m]), scq[k0]);
                float e1 = __fadd_rn(__fmaf_rn(d1, -2.0f, xsq[m]), scq[k0 + 1]);
                if (e0 < bv) { bv = e0; bi = k0; }
                if (e1 < bv) { bv = e1; bi = k0 + 1; }
            }
            sbv[(q + 16 * m) * 33 + g] = bv;
            sbi[(q + 16 * m) * 33 + g] = bi;
        }
        __syncthreads();

        // ---- final per-point argmin over groups (ascending => first-min) ----
        if (tid < 64) {
            float bbv = FLT_BIG; int bbi = 0;
#pragma unroll 8
            for (int gg = 0; gg < 32; gg++) {
                float v = sbv[tid * 33 + gg];
                int   i = sbi[tid * 33 + gg];
                if (v < bbv) { bbv = v; bbi = i; }
            }
            labels[n0 + tid] = (float)bbi;           // float32 output
        }
        __syncthreads();
    }
}

// ---------------- stable counting sort of points by label -------------------------
__global__ void k_hist(const float* __restrict__ labels) {
    __shared__ int h[K_CL];
    const int b = blockIdx.x, tid = threadIdx.x;
    for (int i = tid; i < K_CL; i += 256) h[i] = 0;
    __syncthreads();
    const int s = b * CHUNKB, e = min(N_PTS, s + CHUNKB), m = e - s;
    for (int i = tid; i < m; i += 256) atomicAdd(&h[(int)labels[s + i]], 1);
    __syncthreads();
    for (int i = tid; i < K_CL; i += 256) g_bhist[b][i] = h[i];
}

__global__ void k_scan() {
    __shared__ int stot[K_CL], sbase[K_CL];
    const int k = threadIdx.x;                       // 256 threads, 1 block
    int tot = 0;
    for (int b = 0; b < NSEG; b++) tot += g_bhist[b][k];
    stot[k] = tot;
    __syncthreads();
    if (k == 0) {
        int base = 0;
        for (int i = 0; i < K_CL; i++) { sbase[i] = base; base += stot[i]; }
    }
    __syncthreads();
    int run = sbase[k];
    for (int b = 0; b < NSEG; b++) { g_bbase[b][k] = run; run += g_bhist[b][k]; }
    g_counts[k] = stot[k];
    g_cbase[k]  = sbase[k];
}

__global__ void k_place(const float* __restrict__ labels) {
    __shared__ int slab[CHUNKB];
    __shared__ int cur[K_CL];
    const int b = blockIdx.x, tid = threadIdx.x;
    const int s = b * CHUNKB, e = min(N_PTS, s + CHUNKB), m = e - s;
    for (int i = tid; i < m; i += 256) slab[i] = (int)labels[s + i];
    for (int i = tid; i < K_CL; i += 256) cur[i] = g_bbase[b][i];
    __syncthreads();
    if (tid == 0) {                                  // stable: ascending n within block
        for (int i = 0; i < m; i++) {
            int k = slab[i];
            g_order[cur[k]++] = s + i;
        }
    }
}

// ---------------- per-cluster serial sums (global point order) + center update ----
__global__ void k_sums(const float* __restrict__ x) {
    __shared__ int sidx[2048];
    const int k = blockIdx.x;                        // 256 blocks
    const int f = threadIdx.x;                       // 64 threads
    const int base = g_cbase[k];
    const int cnt  = g_counts[k];
    float acc = 0.f;
    for (int off = 0; off < cnt; off += 2048) {
        const int m = min(2048, cnt - off);
        __syncthreads();
        for (int i = threadIdx.x; i < m; i += 64) sidx[i] = g_order[base + off + i];
        __syncthreads();
        int i = 0;
        for (; i + 8 <= m; i += 8) {                 // batch loads (MLP), serial adds
            float v0 = x[(size_t)sidx[i + 0] * F_DIM + f];
            float v1 = x[(size_t)sidx[i + 1] * F_DIM + f];
            float v2 = x[(size_t)sidx[i + 2] * F_DIM + f];
            float v3 = x[(size_t)sidx[i + 3] * F_DIM + f];
            float v4 = x[(size_t)sidx[i + 4] * F_DIM + f];
            float v5 = x[(size_t)sidx[i + 5] * F_DIM + f];
            float v6 = x[(size_t)sidx[i + 6] * F_DIM + f];
            float v7 = x[(size_t)sidx[i + 7] * F_DIM + f];
            acc = __fadd_rn(acc, v0); acc = __fadd_rn(acc, v1);
            acc = __fadd_rn(acc, v2); acc = __fadd_rn(acc, v3);
            acc = __fadd_rn(acc, v4); acc = __fadd_rn(acc, v5);
            acc = __fadd_rn(acc, v6); acc = __fadd_rn(acc, v7);
        }
        for (; i < m; i++)
            acc = __fadd_rn(acc, x[(size_t)sidx[i] * F_DIM + f]);
    }
    if (cnt > 0)
        g_centers[k * F_DIM + f] = __fdiv_rn(acc, (float)cnt);  // empty keeps old
}

// ---------------- launch ----------------
extern "C" void kernel_launch(void* const* d_in, const int* in_sizes, int n_in,
                              void* d_out, int out_size) {
    const float* x  = nullptr;
    const float* c0 = nullptr;
    for (int i = 0; i < n_in; i++) {
        if (in_sizes[i] == N_PTS * F_DIM)      x  = (const float*)d_in[i];
        else if (in_sizes[i] == K_CL * F_DIM)  c0 = (const float*)d_in[i];
    }
    if (!x)  x  = (const float*)d_in[0];
    if (!c0) c0 = (const float*)d_in[1];
    float* labels = (float*)d_out;                   // __output__ is float32

    int dev = 0, nsm = 0;
    cudaGetDevice(&dev);
    if (cudaDeviceGetAttribute(&nsm, cudaDevAttrMultiProcessorCount, dev) != cudaSuccess || nsm <= 0)
        nsm = 148;

    const size_t asmem = (size_t)C_TOTAL * sizeof(u64)
                       + 64 * X_STRIDE_F * sizeof(float)
                       + K_CL * sizeof(float)
                       + 64 * 33 * (sizeof(float) + sizeof(int));   // ~99 KB
    cudaFuncSetAttribute(k_assign, cudaFuncAttributeMaxDynamicSharedMemorySize, (int)asmem);

    k_init<<<(N_PTS + 255) / 256, 256>>>(x, c0);
    for (int it = 0; it < MAX_ITERS; it++) {
        k_assign<<<nsm, 512, asmem>>>(x, labels);    // csq fused in prologue
        k_hist<<<NSEG, 256>>>(labels);
        k_scan<<<1, K_CL>>>();
        k_place<<<NSEG, 256>>>(labels);
        k_sums<<<K_CL, F_DIM>>>(x);
    }
}